// round 7
// baseline (speedup 1.0000x reference)
#include <cuda_runtime.h>
#include <math.h>

#define BB 16
#define TT 2048
#define EE 64
#define HS 16
#define NQT (TT / 128)    // 16 query tiles
#define NKP 8             // max k-pairs (256-key supertiles) per query tile
#define NPAIR2 72         // sum_{jt=0..15} ceil((jt+1)/2)

typedef unsigned long long u64;

// ---- packed f32x2 helpers (sm_100+) ----
__device__ __forceinline__ u64 ffma2(u64 a, u64 b, u64 c) {
    u64 d; asm("fma.rn.f32x2 %0,%1,%2,%3;" : "=l"(d) : "l"(a), "l"(b), "l"(c)); return d;
}
__device__ __forceinline__ u64 fmul2(u64 a, u64 b) {
    u64 d; asm("mul.rn.f32x2 %0,%1,%2;" : "=l"(d) : "l"(a), "l"(b)); return d;
}
__device__ __forceinline__ u64 fadd2(u64 a, u64 b) {
    u64 d; asm("add.rn.f32x2 %0,%1,%2;" : "=l"(d) : "l"(a), "l"(b)); return d;
}
__device__ __forceinline__ u64 pack2(float x, float y) {
    u64 d; asm("mov.b64 %0,{%1,%2};" : "=l"(d) : "f"(x), "f"(y)); return d;
}
__device__ __forceinline__ float2 unpack2(u64 a) {
    float x, y; asm("mov.b64 {%0,%1},%2;" : "=f"(x), "=f"(y) : "l"(a)); return make_float2(x, y);
}
__device__ __forceinline__ float ex2f(float x) {
    float y; asm("ex2.approx.f32 %0,%1;" : "=f"(y) : "f"(x)); return y;
}

// scratch
__device__ float g_q[BB * TT * HS];
__device__ float g_k[BB * TT * HS];
__device__ float g_v[BB * TT * HS];
__device__ float g_rope[TT * HS];   // [t][2i]=cos, [t][2i+1]=sin
// partials (per 256-key supertile): acc as 4 coalesced float4 fields, (m,l) as float2
__device__ float4 g_part4[BB * NQT * NKP * 4 * 128];
__device__ float2 g_ml[BB * NQT * NKP * 128];

// log2(e) * hs^-0.5
#define QSCALE 0.360673760222241f

// ---------------------------------------------------------------------------
// Kernel 0: RoPE cos/sin table. One thread per (t, i).
// ---------------------------------------------------------------------------
__global__ __launch_bounds__(128) void rope_table_kernel()
{
    int idx = blockIdx.x * 128 + threadIdx.x;   // 0 .. TT*8-1
    int t = idx >> 3;
    int i = idx & 7;
    float inv = powf(10000.0f, -(float)i * (2.0f / (float)HS));
    float sn, cs;
    sincosf((float)t * inv, &sn, &cs);
    g_rope[t * 16 + 2 * i]     = cs;
    g_rope[t * 16 + 2 * i + 1] = sn;
}

// ---------------------------------------------------------------------------
// Kernel 1: fused QKV projection + RoPE (one thread per (b,t) row)
// ---------------------------------------------------------------------------
__global__ __launch_bounds__(128) void qkv_rope_kernel(
    const float* __restrict__ x,
    const float* __restrict__ wq,
    const float* __restrict__ wk,
    const float* __restrict__ wv)
{
    __shared__ float swq[EE * HS];
    __shared__ float swk[EE * HS];
    __shared__ float swv[EE * HS];

    int tid = threadIdx.x;
    for (int i = tid; i < EE * HS; i += 128) {
        swq[i] = wq[i];
        swk[i] = wk[i];
        swv[i] = wv[i];
    }
    __syncthreads();

    int row = blockIdx.x * 128 + tid;
    int t = row & (TT - 1);

    const float4* xr = reinterpret_cast<const float4*>(x + (size_t)row * EE);

    float q[HS], k[HS], v[HS];
#pragma unroll
    for (int h = 0; h < HS; h++) { q[h] = 0.f; k[h] = 0.f; v[h] = 0.f; }

#pragma unroll
    for (int e4 = 0; e4 < EE / 4; e4++) {
        float4 xv = xr[e4];
        float xs[4] = {xv.x, xv.y, xv.z, xv.w};
#pragma unroll
        for (int j = 0; j < 4; j++) {
            int e = e4 * 4 + j;
#pragma unroll
            for (int h = 0; h < HS; h++) {
                q[h] = fmaf(xs[j], swq[e * HS + h], q[h]);
                k[h] = fmaf(xs[j], swk[e * HS + h], k[h]);
                v[h] = fmaf(xs[j], swv[e * HS + h], v[h]);
            }
        }
    }

    const float4* rp = reinterpret_cast<const float4*>(g_rope + t * 16);
    float rope[16];
#pragma unroll
    for (int j = 0; j < 4; j++) {
        float4 rv = rp[j];
        rope[4 * j] = rv.x; rope[4 * j + 1] = rv.y;
        rope[4 * j + 2] = rv.z; rope[4 * j + 3] = rv.w;
    }

    float qo[HS], ko[HS];
#pragma unroll
    for (int i = 0; i < HS / 2; i++) {
        float cs = rope[2 * i], sn = rope[2 * i + 1];
        float qe = q[2 * i], qd = q[2 * i + 1];
        float ke = k[2 * i], kd = k[2 * i + 1];
        qo[2 * i]     = qe * cs - qd * sn;
        qo[2 * i + 1] = qe * sn + qd * cs;
        ko[2 * i]     = ke * cs - kd * sn;
        ko[2 * i + 1] = ke * sn + kd * cs;
    }

    float4* Q4 = reinterpret_cast<float4*>(g_q + (size_t)row * HS);
    float4* K4 = reinterpret_cast<float4*>(g_k + (size_t)row * HS);
    float4* V4 = reinterpret_cast<float4*>(g_v + (size_t)row * HS);
#pragma unroll
    for (int j = 0; j < 4; j++) {
        Q4[j] = make_float4(qo[4 * j], qo[4 * j + 1], qo[4 * j + 2], qo[4 * j + 3]);
        K4[j] = make_float4(ko[4 * j], ko[4 * j + 1], ko[4 * j + 2], ko[4 * j + 3]);
        V4[j] = make_float4(v[4 * j],  v[4 * j + 1],  v[4 * j + 2],  v[4 * j + 3]);
    }
}

// ---------------------------------------------------------------------------
// Kernel 2: partial flash attention, one block per (b, jt, 256-key supertile).
// ---------------------------------------------------------------------------
template <bool DIAG>
__device__ __forceinline__ void tile_body(
    const ulonglong2* __restrict__ sk,
    const ulonglong2* __restrict__ sv,
    const u64* __restrict__ qp,
    u64* __restrict__ acc, float& m, float& l,
    int kmax)
{
#pragma unroll 1
    for (int c0 = 0; c0 < 128; c0 += 16) {
        if (DIAG) { if (c0 > kmax) break; }

        float s[16];
#pragma unroll
        for (int j = 0; j < 16; j++) {
            int key = c0 + j;
            ulonglong2 ka = sk[key * 4 + 0];
            ulonglong2 kb = sk[key * 4 + 1];
            ulonglong2 kc = sk[key * 4 + 2];
            ulonglong2 kd = sk[key * 4 + 3];
            u64 d0 = fmul2(qp[0], ka.x);
            d0 = ffma2(qp[1], ka.y, d0);
            d0 = ffma2(qp[2], kb.x, d0);
            d0 = ffma2(qp[3], kb.y, d0);
            u64 d1 = fmul2(qp[4], kc.x);
            d1 = ffma2(qp[5], kc.y, d1);
            d1 = ffma2(qp[6], kd.x, d1);
            d1 = ffma2(qp[7], kd.y, d1);
            float2 f = unpack2(fadd2(d0, d1));
            float dot = f.x + f.y;
            if (DIAG)
                s[j] = (key <= kmax) ? dot : -1e30f;
            else
                s[j] = dot;
        }

        float cm = s[0];
#pragma unroll
        for (int j = 1; j < 16; j++) cm = fmaxf(cm, s[j]);
        float mn = fmaxf(m, cm);
        float corr = ex2f(m - mn);
        m = mn;
        l *= corr;
        u64 c2 = pack2(corr, corr);
#pragma unroll
        for (int h = 0; h < 8; h++) acc[h] = fmul2(acc[h], c2);

#pragma unroll
        for (int j = 0; j < 16; j++) {
            int key = c0 + j;
            float p = ex2f(s[j] - mn);
            l += p;
            u64 p2 = pack2(p, p);
            ulonglong2 va = sv[key * 4 + 0];
            ulonglong2 vb = sv[key * 4 + 1];
            ulonglong2 vc = sv[key * 4 + 2];
            ulonglong2 vd = sv[key * 4 + 3];
            acc[0] = ffma2(p2, va.x, acc[0]);
            acc[1] = ffma2(p2, va.y, acc[1]);
            acc[2] = ffma2(p2, vb.x, acc[2]);
            acc[3] = ffma2(p2, vb.y, acc[3]);
            acc[4] = ffma2(p2, vc.x, acc[4]);
            acc[5] = ffma2(p2, vc.y, acc[5]);
            acc[6] = ffma2(p2, vd.x, acc[6]);
            acc[7] = ffma2(p2, vd.y, acc[7]);
        }
    }
}

__global__ __launch_bounds__(128) void attn_part_kernel()
{
    int b = blockIdx.y;
    int p = blockIdx.x;

    // decode flat index -> (jt, kp): kp-th 256-key supertile of query tile jt
    int jt = 0, rem = p;
    while (rem >= (jt + 2) / 2) { rem -= (jt + 2) / 2; jt++; }
    int kp = rem;

    int tid = threadIdx.x;
    int t = jt * 128 + tid;
    int kt0 = 2 * kp;
    int k0 = kt0 * 128;

    __shared__ ulonglong2 sk[256 * 4];   // 256 keys
    __shared__ ulonglong2 sv[256 * 4];

    const ulonglong2* Kb = reinterpret_cast<const ulonglong2*>(g_k + (size_t)b * TT * HS);
    const ulonglong2* Vb = reinterpret_cast<const ulonglong2*>(g_v + (size_t)b * TT * HS);
#pragma unroll
    for (int rr = 0; rr < 2; rr++) {
        int r = tid + rr * 128;
#pragma unroll
        for (int j = 0; j < 4; j++) {
            sk[r * 4 + j] = Kb[(size_t)(k0 + r) * 4 + j];
            sv[r * 4 + j] = Vb[(size_t)(k0 + r) * 4 + j];
        }
    }

    const float4* Qr = reinterpret_cast<const float4*>(g_q + ((size_t)b * TT + t) * HS);
    u64 qp[8];
#pragma unroll
    for (int j = 0; j < 4; j++) {
        float4 qv = Qr[j];
        qp[2 * j]     = pack2(qv.x * QSCALE, qv.y * QSCALE);
        qp[2 * j + 1] = pack2(qv.z * QSCALE, qv.w * QSCALE);
    }

    u64 acc[8];
    u64 zz = pack2(0.f, 0.f);
#pragma unroll
    for (int h = 0; h < 8; h++) acc[h] = zz;
    float m = -1e30f, l = 0.f;

    __syncthreads();

    // tile 0 of the supertile
    if (kt0 == jt)
        tile_body<true>(sk, sv, qp, acc, m, l, tid);
    else
        tile_body<false>(sk, sv, qp, acc, m, l, 127);

    // tile 1 (if in causal range)
    if (kt0 + 1 <= jt) {
        if (kt0 + 1 == jt)
            tile_body<true>(sk + 512, sv + 512, qp, acc, m, l, tid);
        else
            tile_body<false>(sk + 512, sv + 512, qp, acc, m, l, 127);
    }

    // write partial
    size_t pb = ((size_t)(b * NQT + jt) * NKP + kp);
    float4* dst = g_part4 + pb * 4 * 128 + tid;
#pragma unroll
    for (int h = 0; h < 4; h++) {
        float2 f0 = unpack2(acc[2 * h]);
        float2 f1 = unpack2(acc[2 * h + 1]);
        dst[h * 128] = make_float4(f0.x, f0.y, f1.x, f1.y);
    }
    g_ml[pb * 128 + tid] = make_float2(m, l);
}

// ---------------------------------------------------------------------------
// Kernel 3: combine partials (m in log2 domain). n <= 8 supertiles.
// ---------------------------------------------------------------------------
__global__ __launch_bounds__(128) void combine_kernel(float* __restrict__ out)
{
    int jt = blockIdx.x;
    int b  = blockIdx.y;
    int tid = threadIdx.x;
    int n = (jt + 2) / 2;

    const float4* base = g_part4 + (size_t)(b * NQT + jt) * NKP * 4 * 128 + tid;
    const float2* mlb  = g_ml    + (size_t)(b * NQT + jt) * NKP * 128 + tid;

    // all (m,l) in flight at once
    float2 ml[NKP];
#pragma unroll
    for (int i = 0; i < NKP; i++)
        ml[i] = (i < n) ? mlb[i * 128] : make_float2(-1e30f, 0.f);

    float m_tot = ml[0].x;
#pragma unroll
    for (int i = 1; i < NKP; i++) m_tot = fmaxf(m_tot, ml[i].x);

    float acc[HS];
#pragma unroll
    for (int h = 0; h < HS; h++) acc[h] = 0.f;
    float l_tot = 0.f;

#pragma unroll 2
    for (int i = 0; i < n; i++) {
        const float4* pp = base + (size_t)i * 4 * 128;
        float4 a0 = pp[0];
        float4 a1 = pp[128];
        float4 a2 = pp[256];
        float4 a3 = pp[384];
        float w = ex2f(ml[i].x - m_tot);
        l_tot = fmaf(ml[i].y, w, l_tot);
        acc[0]  = fmaf(a0.x, w, acc[0]);
        acc[1]  = fmaf(a0.y, w, acc[1]);
        acc[2]  = fmaf(a0.z, w, acc[2]);
        acc[3]  = fmaf(a0.w, w, acc[3]);
        acc[4]  = fmaf(a1.x, w, acc[4]);
        acc[5]  = fmaf(a1.y, w, acc[5]);
        acc[6]  = fmaf(a1.z, w, acc[6]);
        acc[7]  = fmaf(a1.w, w, acc[7]);
        acc[8]  = fmaf(a2.x, w, acc[8]);
        acc[9]  = fmaf(a2.y, w, acc[9]);
        acc[10] = fmaf(a2.z, w, acc[10]);
        acc[11] = fmaf(a2.w, w, acc[11]);
        acc[12] = fmaf(a3.x, w, acc[12]);
        acc[13] = fmaf(a3.y, w, acc[13]);
        acc[14] = fmaf(a3.z, w, acc[14]);
        acc[15] = fmaf(a3.w, w, acc[15]);
    }

    float inv_l = 1.0f / l_tot;
    int t = jt * 128 + tid;
    float4* Or = reinterpret_cast<float4*>(out + ((size_t)b * TT + t) * HS);
#pragma unroll
    for (int j = 0; j < 4; j++)
        Or[j] = make_float4(acc[4 * j] * inv_l, acc[4 * j + 1] * inv_l,
                            acc[4 * j + 2] * inv_l, acc[4 * j + 3] * inv_l);
}

extern "C" void kernel_launch(void* const* d_in, const int* in_sizes, int n_in,
                              void* d_out, int out_size)
{
    const float* x  = (const float*)d_in[0];
    const float* wq = (const float*)d_in[1];
    const float* wk = (const float*)d_in[2];
    const float* wv = (const float*)d_in[3];
    float* out = (float*)d_out;

    rope_table_kernel<<<(TT * 8) / 128, 128>>>();
    qkv_rope_kernel<<<(BB * TT) / 128, 128>>>(x, wq, wk, wv);

    dim3 grid_p(NPAIR2, BB);
    attn_part_kernel<<<grid_p, 128>>>();

    dim3 grid_c(NQT, BB);
    combine_kernel<<<grid_c, 128>>>(out);
}

// round 8
// speedup vs baseline: 1.7262x; 1.7262x over previous
#include <cuda_runtime.h>
#include <math.h>
#include <stdint.h>

#define BB 16
#define TT 2048
#define EE 64
#define HS 16
#define NQT (TT / 128)    // 16 query tiles
#define NKP 8             // max 256-key supertiles per query tile
#define NPAIR2 72         // sum_{jt=0..15} ceil((jt+1)/2)

// log2(e) * hs^-0.5
#define QSCALE 0.360673760222241f

// scratch
__device__ float g_q[BB * TT * HS];
__device__ float g_k[BB * TT * HS];
__device__ float g_v[BB * TT * HS];
__device__ float g_rope[TT * HS];
// partials: acc as 4 coalesced float4 fields, (m,l) as float2 (m in log2 domain)
__device__ float4 g_part4[BB * NQT * NKP * 4 * 128];
__device__ float2 g_ml[BB * NQT * NKP * 128];

// ---- helpers ----
__device__ __forceinline__ float ex2f(float x) {
    float y; asm("ex2.approx.f32 %0,%1;" : "=f"(y) : "f"(x)); return y;
}
// pack: low half = lo element, high half = hi element (PTX: first operand -> high)
__device__ __forceinline__ uint32_t cvt_bf16x2(float hi, float lo) {
    uint32_t d; asm("cvt.rn.bf16x2.f32 %0,%1,%2;" : "=r"(d) : "f"(hi), "f"(lo)); return d;
}
__device__ __forceinline__ float bf_lo_f32(uint32_t p) { return __uint_as_float(p << 16); }
__device__ __forceinline__ float bf_hi_f32(uint32_t p) { return __uint_as_float(p & 0xFFFF0000u); }
// split (f0,f1) into hi/lo bf16x2 packs (f0 -> low half)
__device__ __forceinline__ void split2(float f0, float f1, uint32_t& hi, uint32_t& lo) {
    hi = cvt_bf16x2(f1, f0);
    lo = cvt_bf16x2(f1 - bf_hi_f32(hi), f0 - bf_lo_f32(hi));
}
__device__ __forceinline__ void mma_bf16(float c[4],
    uint32_t a0, uint32_t a1, uint32_t a2, uint32_t a3, uint32_t b0, uint32_t b1) {
    asm volatile(
        "mma.sync.aligned.m16n8k16.row.col.f32.bf16.bf16.f32 "
        "{%0,%1,%2,%3},{%4,%5,%6,%7},{%8,%9},{%0,%1,%2,%3};"
        : "+f"(c[0]), "+f"(c[1]), "+f"(c[2]), "+f"(c[3])
        : "r"(a0), "r"(a1), "r"(a2), "r"(a3), "r"(b0), "r"(b1));
}

// ---------------------------------------------------------------------------
// Kernel 0: RoPE cos/sin table
// ---------------------------------------------------------------------------
__global__ __launch_bounds__(128) void rope_table_kernel()
{
    int idx = blockIdx.x * 128 + threadIdx.x;
    int t = idx >> 3;
    int i = idx & 7;
    float inv = powf(10000.0f, -(float)i * (2.0f / (float)HS));
    float sn, cs;
    sincosf((float)t * inv, &sn, &cs);
    g_rope[t * 16 + 2 * i]     = cs;
    g_rope[t * 16 + 2 * i + 1] = sn;
}

// ---------------------------------------------------------------------------
// Kernel 1: fused QKV projection + RoPE
// ---------------------------------------------------------------------------
__global__ __launch_bounds__(128) void qkv_rope_kernel(
    const float* __restrict__ x,
    const float* __restrict__ wq,
    const float* __restrict__ wk,
    const float* __restrict__ wv)
{
    __shared__ float swq[EE * HS];
    __shared__ float swk[EE * HS];
    __shared__ float swv[EE * HS];

    int tid = threadIdx.x;
    for (int i = tid; i < EE * HS; i += 128) {
        swq[i] = wq[i]; swk[i] = wk[i]; swv[i] = wv[i];
    }
    __syncthreads();

    int row = blockIdx.x * 128 + tid;
    int t = row & (TT - 1);

    const float4* xr = reinterpret_cast<const float4*>(x + (size_t)row * EE);

    float q[HS], k[HS], v[HS];
#pragma unroll
    for (int h = 0; h < HS; h++) { q[h] = 0.f; k[h] = 0.f; v[h] = 0.f; }

#pragma unroll
    for (int e4 = 0; e4 < EE / 4; e4++) {
        float4 xv = xr[e4];
        float xs[4] = {xv.x, xv.y, xv.z, xv.w};
#pragma unroll
        for (int j = 0; j < 4; j++) {
            int e = e4 * 4 + j;
#pragma unroll
            for (int h = 0; h < HS; h++) {
                q[h] = fmaf(xs[j], swq[e * HS + h], q[h]);
                k[h] = fmaf(xs[j], swk[e * HS + h], k[h]);
                v[h] = fmaf(xs[j], swv[e * HS + h], v[h]);
            }
        }
    }

    const float4* rp = reinterpret_cast<const float4*>(g_rope + t * 16);
    float rope[16];
#pragma unroll
    for (int j = 0; j < 4; j++) {
        float4 rv = rp[j];
        rope[4 * j] = rv.x; rope[4 * j + 1] = rv.y;
        rope[4 * j + 2] = rv.z; rope[4 * j + 3] = rv.w;
    }

    float qo[HS], ko[HS];
#pragma unroll
    for (int i = 0; i < HS / 2; i++) {
        float cs = rope[2 * i], sn = rope[2 * i + 1];
        float qe = q[2 * i], qd = q[2 * i + 1];
        float ke = k[2 * i], kd = k[2 * i + 1];
        qo[2 * i]     = qe * cs - qd * sn;
        qo[2 * i + 1] = qe * sn + qd * cs;
        ko[2 * i]     = ke * cs - kd * sn;
        ko[2 * i + 1] = ke * sn + kd * cs;
    }

    float4* Q4 = reinterpret_cast<float4*>(g_q + (size_t)row * HS);
    float4* K4 = reinterpret_cast<float4*>(g_k + (size_t)row * HS);
    float4* V4 = reinterpret_cast<float4*>(g_v + (size_t)row * HS);
#pragma unroll
    for (int j = 0; j < 4; j++) {
        Q4[j] = make_float4(qo[4 * j], qo[4 * j + 1], qo[4 * j + 2], qo[4 * j + 3]);
        K4[j] = make_float4(ko[4 * j], ko[4 * j + 1], ko[4 * j + 2], ko[4 * j + 3]);
        V4[j] = make_float4(v[4 * j],  v[4 * j + 1],  v[4 * j + 2],  v[4 * j + 3]);
    }
}

// ---------------------------------------------------------------------------
// Kernel 2: tensor-core flash attention partial, one block per
// (b, jt, 256-key supertile). 4 warps x 32 queries. bf16 split-precision mma.
// ---------------------------------------------------------------------------
template <bool DIAG>
__device__ __forceinline__ void attn_body(
    int b, int jt, int kp,
    const uint2 (*sKhi)[32], const uint2 (*sKlo)[32],
    const uint2 (*sVhi)[2][32], const uint2 (*sVlo)[2][32],
    float (*sOut)[17], float2* sML)
{
    int tid = threadIdx.x;
    int w = tid >> 5;
    int lane = tid & 31;
    int g = lane >> 2;
    int t4 = lane & 3;
    int st = kp * 256;
    int qwbase = jt * 128 + w * 32;

    // ---- load Q fragments (hi/lo), scaled by QSCALE ----
    uint32_t qA_hi[2][4], qA_lo[2][4];
#pragma unroll
    for (int mt = 0; mt < 2; mt++) {
        int r0 = qwbase + 16 * mt + g;
        const float* Q0 = g_q + ((size_t)b * TT + r0) * HS;
        const float* Q1 = g_q + ((size_t)b * TT + r0 + 8) * HS;
        float2 f00 = *reinterpret_cast<const float2*>(Q0 + 2 * t4);
        float2 f01 = *reinterpret_cast<const float2*>(Q0 + 2 * t4 + 8);
        float2 f10 = *reinterpret_cast<const float2*>(Q1 + 2 * t4);
        float2 f11 = *reinterpret_cast<const float2*>(Q1 + 2 * t4 + 8);
        split2(f00.x * QSCALE, f00.y * QSCALE, qA_hi[mt][0], qA_lo[mt][0]);
        split2(f10.x * QSCALE, f10.y * QSCALE, qA_hi[mt][1], qA_lo[mt][1]);
        split2(f01.x * QSCALE, f01.y * QSCALE, qA_hi[mt][2], qA_lo[mt][2]);
        split2(f11.x * QSCALE, f11.y * QSCALE, qA_hi[mt][3], qA_lo[mt][3]);
    }

    float m[4], l[4], acc[2][2][4];
#pragma unroll
    for (int r = 0; r < 4; r++) { m[r] = -1e30f; l[r] = 0.f; }
#pragma unroll
    for (int mt = 0; mt < 2; mt++)
#pragma unroll
        for (int hn = 0; hn < 2; hn++)
#pragma unroll
            for (int r = 0; r < 4; r++) acc[mt][hn][r] = 0.f;

    int nchunks = 8;
    if (DIAG) {
        int qmaxw = qwbase + 31;
        nchunks = ((qmaxw - st) >> 5) + 1;
        if (nchunks > 8) nchunks = 8;
    }

    for (int c = 0; c < nchunks; c++) {
        // ---- QK^T: 4 n-tiles x 2 m-tiles, 3 split mmas each ----
        float s[4][2][4];
#pragma unroll
        for (int ntl = 0; ntl < 4; ntl++) {
            int nt = c * 4 + ntl;
            uint2 kh = sKhi[nt][lane];
            uint2 kl = sKlo[nt][lane];
#pragma unroll
            for (int mt = 0; mt < 2; mt++) {
                s[ntl][mt][0] = 0.f; s[ntl][mt][1] = 0.f;
                s[ntl][mt][2] = 0.f; s[ntl][mt][3] = 0.f;
                mma_bf16(s[ntl][mt], qA_hi[mt][0], qA_hi[mt][1], qA_hi[mt][2], qA_hi[mt][3], kh.x, kh.y);
                mma_bf16(s[ntl][mt], qA_hi[mt][0], qA_hi[mt][1], qA_hi[mt][2], qA_hi[mt][3], kl.x, kl.y);
                mma_bf16(s[ntl][mt], qA_lo[mt][0], qA_lo[mt][1], qA_lo[mt][2], qA_lo[mt][3], kh.x, kh.y);
            }
        }

        if (DIAG) {
#pragma unroll
            for (int ntl = 0; ntl < 4; ntl++) {
                int kb = st + (c * 4 + ntl) * 8 + 2 * t4;
#pragma unroll
                for (int mt = 0; mt < 2; mt++) {
                    int r0 = qwbase + 16 * mt + g;
                    if (kb     > r0)     s[ntl][mt][0] = -1e30f;
                    if (kb + 1 > r0)     s[ntl][mt][1] = -1e30f;
                    if (kb     > r0 + 8) s[ntl][mt][2] = -1e30f;
                    if (kb + 1 > r0 + 8) s[ntl][mt][3] = -1e30f;
                }
            }
        }

        // ---- online softmax on fragments ----
        float cmax[4];
#pragma unroll
        for (int r = 0; r < 4; r++) cmax[r] = -1e30f;
#pragma unroll
        for (int ntl = 0; ntl < 4; ntl++)
#pragma unroll
            for (int mt = 0; mt < 2; mt++) {
                cmax[mt * 2]     = fmaxf(cmax[mt * 2],     fmaxf(s[ntl][mt][0], s[ntl][mt][1]));
                cmax[mt * 2 + 1] = fmaxf(cmax[mt * 2 + 1], fmaxf(s[ntl][mt][2], s[ntl][mt][3]));
            }
#pragma unroll
        for (int r = 0; r < 4; r++) {
            cmax[r] = fmaxf(cmax[r], __shfl_xor_sync(0xffffffffu, cmax[r], 1));
            cmax[r] = fmaxf(cmax[r], __shfl_xor_sync(0xffffffffu, cmax[r], 2));
        }
        float corr[4];
#pragma unroll
        for (int r = 0; r < 4; r++) {
            float mn = fmaxf(m[r], cmax[r]);
            corr[r] = ex2f(m[r] - mn);
            m[r] = mn;
            l[r] *= corr[r];
        }
#pragma unroll
        for (int mt = 0; mt < 2; mt++)
#pragma unroll
            for (int hn = 0; hn < 2; hn++) {
                acc[mt][hn][0] *= corr[mt * 2];
                acc[mt][hn][1] *= corr[mt * 2];
                acc[mt][hn][2] *= corr[mt * 2 + 1];
                acc[mt][hn][3] *= corr[mt * 2 + 1];
            }

        // ---- P = ex2(s-m), split to bf16 hi/lo A-fragments ----
        // A-frag for PV kstep ks: a0 = (row g,  keys of ntile 2ks   c0,c1)
        //                          a1 = (row g+8, ntile 2ks c2,c3)
        //                          a2 = (row g,  ntile 2ks+1 c0,c1)
        //                          a3 = (row g+8, ntile 2ks+1 c2,c3)
        uint32_t pa_hi[2][2][4], pa_lo[2][2][4];   // [ks][mt][reg]
#pragma unroll
        for (int ntl = 0; ntl < 4; ntl++) {
            int ks = ntl >> 1;
            int half = ntl & 1;
#pragma unroll
            for (int mt = 0; mt < 2; mt++) {
                float p0 = ex2f(s[ntl][mt][0] - m[mt * 2]);
                float p1 = ex2f(s[ntl][mt][1] - m[mt * 2]);
                float p2 = ex2f(s[ntl][mt][2] - m[mt * 2 + 1]);
                float p3 = ex2f(s[ntl][mt][3] - m[mt * 2 + 1]);
                l[mt * 2]     += p0 + p1;
                l[mt * 2 + 1] += p2 + p3;
                split2(p0, p1, pa_hi[ks][mt][0 + 2 * half], pa_lo[ks][mt][0 + 2 * half]);
                split2(p2, p3, pa_hi[ks][mt][1 + 2 * half], pa_lo[ks][mt][1 + 2 * half]);
            }
        }

        // ---- PV: 2 ksteps x 2 hs-tiles x 2 m-tiles, 3 split mmas each ----
#pragma unroll
        for (int ks = 0; ks < 2; ks++) {
            int kstep = c * 2 + ks;
#pragma unroll
            for (int hn = 0; hn < 2; hn++) {
                uint2 vh = sVhi[kstep][hn][lane];
                uint2 vl = sVlo[kstep][hn][lane];
#pragma unroll
                for (int mt = 0; mt < 2; mt++) {
                    mma_bf16(acc[mt][hn], pa_hi[ks][mt][0], pa_hi[ks][mt][1], pa_hi[ks][mt][2], pa_hi[ks][mt][3], vh.x, vh.y);
                    mma_bf16(acc[mt][hn], pa_lo[ks][mt][0], pa_lo[ks][mt][1], pa_lo[ks][mt][2], pa_lo[ks][mt][3], vh.x, vh.y);
                    mma_bf16(acc[mt][hn], pa_hi[ks][mt][0], pa_hi[ks][mt][1], pa_hi[ks][mt][2], pa_hi[ks][mt][3], vl.x, vl.y);
                }
            }
        }
    }

    // ---- reduce l across the 4-thread group ----
#pragma unroll
    for (int r = 0; r < 4; r++) {
        l[r] += __shfl_xor_sync(0xffffffffu, l[r], 1);
        l[r] += __shfl_xor_sync(0xffffffffu, l[r], 2);
    }

    // ---- epilog via smem transpose ----
#pragma unroll
    for (int mt = 0; mt < 2; mt++) {
        int rl = w * 32 + 16 * mt + g;
#pragma unroll
        for (int hn = 0; hn < 2; hn++) {
            int d = hn * 8 + 2 * t4;
            sOut[rl][d]         = acc[mt][hn][0];
            sOut[rl][d + 1]     = acc[mt][hn][1];
            sOut[rl + 8][d]     = acc[mt][hn][2];
            sOut[rl + 8][d + 1] = acc[mt][hn][3];
        }
        sML[rl]     = make_float2(m[mt * 2],     l[mt * 2]);
        sML[rl + 8] = make_float2(m[mt * 2 + 1], l[mt * 2 + 1]);
    }
    __syncthreads();

    size_t pb = ((size_t)(b * NQT + jt) * NKP + kp);
    float4* dst = g_part4 + pb * 4 * 128 + tid;
#pragma unroll
    for (int h = 0; h < 4; h++)
        dst[h * 128] = make_float4(sOut[tid][4 * h], sOut[tid][4 * h + 1],
                                   sOut[tid][4 * h + 2], sOut[tid][4 * h + 3]);
    g_ml[pb * 128 + tid] = sML[tid];
}

__global__ __launch_bounds__(128) void attn_part_kernel()
{
    __shared__ uint2 sKhi[32][32];
    __shared__ uint2 sKlo[32][32];
    __shared__ uint2 sVhi[16][2][32];
    __shared__ uint2 sVlo[16][2][32];
    __shared__ float sOut[128][17];
    __shared__ float2 sML[128];

    int b = blockIdx.y;
    int p = blockIdx.x;
    int jt = 0, rem = p;
    while (rem >= (jt + 2) / 2) { rem -= (jt + 2) / 2; jt++; }
    int kp = rem;
    int st = kp * 256;
    int tid = threadIdx.x;

    // ---- prolog: pack K fragments (b0,b1 for hi and lo) ----
    // K-frag entry (nt, lane): b0 = K[st+nt*8+(lane>>2)][2(lane&3), +1]
    //                          b1 = same key, dims +8
    for (int idx = tid; idx < 32 * 32; idx += 128) {
        int nt = idx >> 5, ln = idx & 31;
        int key = st + nt * 8 + (ln >> 2);
        int d0 = 2 * (ln & 3);
        const float* Kr = g_k + ((size_t)b * TT + key) * HS;
        float2 k0 = *reinterpret_cast<const float2*>(Kr + d0);
        float2 k1 = *reinterpret_cast<const float2*>(Kr + d0 + 8);
        uint32_t h0, l0, h1, l1;
        split2(k0.x, k0.y, h0, l0);
        split2(k1.x, k1.y, h1, l1);
        sKhi[nt][ln] = make_uint2(h0, h1);
        sKlo[nt][ln] = make_uint2(l0, l1);
    }

    // ---- prolog: pack V fragments ----
    // V-frag entry (ks, hn, lane): dim = hn*8 + (lane>>2)
    //   b0 = { V[st+ks*16+2(lane&3)][dim], V[..+1][dim] }
    //   b1 = keys +8, +9
    for (int idx = tid; idx < 16 * 2 * 32; idx += 128) {
        int ks = idx >> 6, rest = idx & 63;
        int hn = rest >> 5, ln = rest & 31;
        int dim = hn * 8 + (ln >> 2);
        int key0 = st + ks * 16 + 2 * (ln & 3);
        const float* Vb = g_v + (size_t)b * TT * HS + dim;
        float v0 = Vb[(size_t)key0 * HS];
        float v1 = Vb[(size_t)(key0 + 1) * HS];
        float v2 = Vb[(size_t)(key0 + 8) * HS];
        float v3 = Vb[(size_t)(key0 + 9) * HS];
        uint32_t h0, l0, h1, l1;
        split2(v0, v1, h0, l0);
        split2(v2, v3, h1, l1);
        sVhi[ks][hn][ln] = make_uint2(h0, h1);
        sVlo[ks][hn][ln] = make_uint2(l0, l1);
    }
    __syncthreads();

    if (kp == (jt >> 1))
        attn_body<true>(b, jt, kp, sKhi, sKlo, sVhi, sVlo, sOut, sML);
    else
        attn_body<false>(b, jt, kp, sKhi, sKlo, sVhi, sVlo, sOut, sML);
}

// ---------------------------------------------------------------------------
// Kernel 3: combine partials (m in log2 domain). n <= 8 supertiles.
// ---------------------------------------------------------------------------
__global__ __launch_bounds__(128) void combine_kernel(float* __restrict__ out)
{
    int jt = blockIdx.x;
    int b  = blockIdx.y;
    int tid = threadIdx.x;
    int n = (jt + 2) / 2;

    const float4* base = g_part4 + (size_t)(b * NQT + jt) * NKP * 4 * 128 + tid;
    const float2* mlb  = g_ml    + (size_t)(b * NQT + jt) * NKP * 128 + tid;

    float2 ml[NKP];
#pragma unroll
    for (int i = 0; i < NKP; i++)
        ml[i] = (i < n) ? mlb[i * 128] : make_float2(-1e30f, 0.f);

    float m_tot = ml[0].x;
#pragma unroll
    for (int i = 1; i < NKP; i++) m_tot = fmaxf(m_tot, ml[i].x);

    float acc[HS];
#pragma unroll
    for (int h = 0; h < HS; h++) acc[h] = 0.f;
    float l_tot = 0.f;

#pragma unroll 2
    for (int i = 0; i < n; i++) {
        const float4* pp = base + (size_t)i * 4 * 128;
        float4 a0 = pp[0];
        float4 a1 = pp[128];
        float4 a2 = pp[256];
        float4 a3 = pp[384];
        float w = ex2f(ml[i].x - m_tot);
        l_tot = fmaf(ml[i].y, w, l_tot);
        acc[0]  = fmaf(a0.x, w, acc[0]);
        acc[1]  = fmaf(a0.y, w, acc[1]);
        acc[2]  = fmaf(a0.z, w, acc[2]);
        acc[3]  = fmaf(a0.w, w, acc[3]);
        acc[4]  = fmaf(a1.x, w, acc[4]);
        acc[5]  = fmaf(a1.y, w, acc[5]);
        acc[6]  = fmaf(a1.z, w, acc[6]);
        acc[7]  = fmaf(a1.w, w, acc[7]);
        acc[8]  = fmaf(a2.x, w, acc[8]);
        acc[9]  = fmaf(a2.y, w, acc[9]);
        acc[10] = fmaf(a2.z, w, acc[10]);
        acc[11] = fmaf(a2.w, w, acc[11]);
        acc[12] = fmaf(a3.x, w, acc[12]);
        acc[13] = fmaf(a3.y, w, acc[13]);
        acc[14] = fmaf(a3.z, w, acc[14]);
        acc[15] = fmaf(a3.w, w, acc[15]);
    }

    float inv_l = 1.0f / l_tot;
    int t = jt * 128 + tid;
    float4* Or = reinterpret_cast<float4*>(out + ((size_t)b * TT + t) * HS);
#pragma unroll
    for (int j = 0; j < 4; j++)
        Or[j] = make_float4(acc[4 * j] * inv_l, acc[4 * j + 1] * inv_l,
                            acc[4 * j + 2] * inv_l, acc[4 * j + 3] * inv_l);
}

extern "C" void kernel_launch(void* const* d_in, const int* in_sizes, int n_in,
                              void* d_out, int out_size)
{
    const float* x  = (const float*)d_in[0];
    const float* wq = (const float*)d_in[1];
    const float* wk = (const float*)d_in[2];
    const float* wv = (const float*)d_in[3];
    float* out = (float*)d_out;

    rope_table_kernel<<<(TT * 8) / 128, 128>>>();
    qkv_rope_kernel<<<(BB * TT) / 128, 128>>>(x, wq, wk, wv);

    dim3 grid_p(NPAIR2, BB);
    attn_part_kernel<<<grid_p, 128>>>();

    dim3 grid_c(NQT, BB);
    combine_kernel<<<grid_c, 128>>>(out);
}

// round 10
// speedup vs baseline: 1.9820x; 1.1482x over previous
#include <cuda_runtime.h>
#include <math.h>
#include <stdint.h>

#define BB 16
#define TT 2048
#define EE 64
#define HS 16
#define NQT (TT / 128)    // 16 query tiles
#define NKP 4             // max 512-key supertiles per query tile
#define NPAIR4 40         // sum_{jt=0..15} (jt/4 + 1)

// log2(e) * hs^-0.5
#define QSCALE 0.360673760222241f

// scratch
__device__ float g_q[BB * TT * HS];
__device__ float g_k[BB * TT * HS];
__device__ float g_v[BB * TT * HS];
__device__ float g_rope[TT * HS];
// partials: acc as 4 coalesced float4 fields, (m,l) as float2 (m in log2 domain)
__device__ float4 g_part4[BB * NQT * NKP * 4 * 128];
__device__ float2 g_ml[BB * NQT * NKP * 128];

// ---- helpers ----
__device__ __forceinline__ float ex2f(float x) {
    float y; asm("ex2.approx.f32 %0,%1;" : "=f"(y) : "f"(x)); return y;
}
// first operand -> HIGH half, second -> LOW half
__device__ __forceinline__ uint32_t cvt_f16x2(float hi, float lo) {
    uint32_t d; asm("cvt.rn.f16x2.f32 %0,%1,%2;" : "=r"(d) : "f"(hi), "f"(lo)); return d;
}
__device__ __forceinline__ void mma_f16(float c[4],
    uint32_t a0, uint32_t a1, uint32_t a2, uint32_t a3, uint32_t b0, uint32_t b1) {
    asm volatile(
        "mma.sync.aligned.m16n8k16.row.col.f32.f16.f16.f32 "
        "{%0,%1,%2,%3},{%4,%5,%6,%7},{%8,%9},{%0,%1,%2,%3};"
        : "+f"(c[0]), "+f"(c[1]), "+f"(c[2]), "+f"(c[3])
        : "r"(a0), "r"(a1), "r"(a2), "r"(a3), "r"(b0), "r"(b1));
}

// ---------------------------------------------------------------------------
// Kernel 0: RoPE cos/sin table
// ---------------------------------------------------------------------------
__global__ __launch_bounds__(128) void rope_table_kernel()
{
    int idx = blockIdx.x * 128 + threadIdx.x;
    int t = idx >> 3;
    int i = idx & 7;
    float inv = powf(10000.0f, -(float)i * (2.0f / (float)HS));
    float sn, cs;
    sincosf((float)t * inv, &sn, &cs);
    g_rope[t * 16 + 2 * i]     = cs;
    g_rope[t * 16 + 2 * i + 1] = sn;
}

// ---------------------------------------------------------------------------
// Kernel 1: fused QKV projection + RoPE. One thread per (row, half):
// blockIdx.y selects head-dim half (8 dims) -> 2x parallelism vs round 8.
// ---------------------------------------------------------------------------
__global__ __launch_bounds__(128) void qkv_rope_kernel(
    const float* __restrict__ x,
    const float* __restrict__ wq,
    const float* __restrict__ wk,
    const float* __restrict__ wv)
{
    __shared__ float swq[EE * 8];
    __shared__ float swk[EE * 8];
    __shared__ float swv[EE * 8];

    int tid = threadIdx.x;
    int half = blockIdx.y;
    int hbase = half * 8;

    for (int i = tid; i < EE * 8; i += 128) {
        int e = i >> 3, h = i & 7;
        swq[i] = wq[e * HS + hbase + h];
        swk[i] = wk[e * HS + hbase + h];
        swv[i] = wv[e * HS + hbase + h];
    }
    __syncthreads();

    int row = blockIdx.x * 128 + tid;
    int t = row & (TT - 1);

    const float4* xr = reinterpret_cast<const float4*>(x + (size_t)row * EE);

    float q[8], k[8], v[8];
#pragma unroll
    for (int h = 0; h < 8; h++) { q[h] = 0.f; k[h] = 0.f; v[h] = 0.f; }

#pragma unroll
    for (int e4 = 0; e4 < EE / 4; e4++) {
        float4 xv = xr[e4];
        float xs[4] = {xv.x, xv.y, xv.z, xv.w};
#pragma unroll
        for (int j = 0; j < 4; j++) {
            int e = e4 * 4 + j;
#pragma unroll
            for (int h = 0; h < 8; h++) {
                q[h] = fmaf(xs[j], swq[e * 8 + h], q[h]);
                k[h] = fmaf(xs[j], swk[e * 8 + h], k[h]);
                v[h] = fmaf(xs[j], swv[e * 8 + h], v[h]);
            }
        }
    }

    // RoPE: this half covers rotation pairs i = half*4 .. half*4+3
    const float4* rp = reinterpret_cast<const float4*>(g_rope + t * 16 + hbase);
    float rope[8];
    {
        float4 r0 = rp[0], r1 = rp[1];
        rope[0] = r0.x; rope[1] = r0.y; rope[2] = r0.z; rope[3] = r0.w;
        rope[4] = r1.x; rope[5] = r1.y; rope[6] = r1.z; rope[7] = r1.w;
    }

    float qo[8], ko[8];
#pragma unroll
    for (int i = 0; i < 4; i++) {
        float cs = rope[2 * i], sn = rope[2 * i + 1];
        float qe = q[2 * i], qd = q[2 * i + 1];
        float ke = k[2 * i], kd = k[2 * i + 1];
        qo[2 * i]     = qe * cs - qd * sn;
        qo[2 * i + 1] = qe * sn + qd * cs;
        ko[2 * i]     = ke * cs - kd * sn;
        ko[2 * i + 1] = ke * sn + kd * cs;
    }

    float4* Q4 = reinterpret_cast<float4*>(g_q + (size_t)row * HS + hbase);
    float4* K4 = reinterpret_cast<float4*>(g_k + (size_t)row * HS + hbase);
    float4* V4 = reinterpret_cast<float4*>(g_v + (size_t)row * HS + hbase);
    Q4[0] = make_float4(qo[0], qo[1], qo[2], qo[3]);
    Q4[1] = make_float4(qo[4], qo[5], qo[6], qo[7]);
    K4[0] = make_float4(ko[0], ko[1], ko[2], ko[3]);
    K4[1] = make_float4(ko[4], ko[5], ko[6], ko[7]);
    V4[0] = make_float4(v[0], v[1], v[2], v[3]);
    V4[1] = make_float4(v[4], v[5], v[6], v[7]);
}

// ---------------------------------------------------------------------------
// Kernel 2: tensor-core flash attention partial, one block per
// (b, jt, 512-key supertile). 4 warps x 32 queries. Single-pass fp16 mma.
// ---------------------------------------------------------------------------
template <bool DIAG>
__device__ __forceinline__ void attn_body(
    int b, int jt, int kp,
    const uint2 (*sK)[32], const uint2 (*sV)[2][32],
    float (*sOut)[17], float2* sML)
{
    int tid = threadIdx.x;
    int w = tid >> 5;
    int lane = tid & 31;
    int g = lane >> 2;
    int t4 = lane & 3;
    int st = kp * 512;
    int qwbase = jt * 128 + w * 32;

    // ---- load Q fragments (fp16, scaled by QSCALE) ----
    uint32_t qA[2][4];
#pragma unroll
    for (int mt = 0; mt < 2; mt++) {
        int r0 = qwbase + 16 * mt + g;
        const float* Q0 = g_q + ((size_t)b * TT + r0) * HS;
        const float* Q1 = g_q + ((size_t)b * TT + r0 + 8) * HS;
        float2 f00 = *reinterpret_cast<const float2*>(Q0 + 2 * t4);
        float2 f01 = *reinterpret_cast<const float2*>(Q0 + 2 * t4 + 8);
        float2 f10 = *reinterpret_cast<const float2*>(Q1 + 2 * t4);
        float2 f11 = *reinterpret_cast<const float2*>(Q1 + 2 * t4 + 8);
        qA[mt][0] = cvt_f16x2(f00.y * QSCALE, f00.x * QSCALE);
        qA[mt][1] = cvt_f16x2(f10.y * QSCALE, f10.x * QSCALE);
        qA[mt][2] = cvt_f16x2(f01.y * QSCALE, f01.x * QSCALE);
        qA[mt][3] = cvt_f16x2(f11.y * QSCALE, f11.x * QSCALE);
    }

    float m[4], l[4], acc[2][2][4];
#pragma unroll
    for (int r = 0; r < 4; r++) { m[r] = -1e30f; l[r] = 0.f; }
#pragma unroll
    for (int mt = 0; mt < 2; mt++)
#pragma unroll
        for (int hn = 0; hn < 2; hn++)
#pragma unroll
            for (int r = 0; r < 4; r++) acc[mt][hn][r] = 0.f;

    int nchunks = 16;
    if (DIAG) {
        int qmaxw = qwbase + 31;
        nchunks = ((qmaxw - st) >> 5) + 1;
        if (nchunks > 16) nchunks = 16;
    }

    for (int c = 0; c < nchunks; c++) {
        // ---- QK^T: 4 n-tiles x 2 m-tiles, 1 fp16 mma each ----
        float s[4][2][4];
#pragma unroll
        for (int ntl = 0; ntl < 4; ntl++) {
            int nt = c * 4 + ntl;
            uint2 kf = sK[nt][lane];
#pragma unroll
            for (int mt = 0; mt < 2; mt++) {
                s[ntl][mt][0] = 0.f; s[ntl][mt][1] = 0.f;
                s[ntl][mt][2] = 0.f; s[ntl][mt][3] = 0.f;
                mma_f16(s[ntl][mt], qA[mt][0], qA[mt][1], qA[mt][2], qA[mt][3], kf.x, kf.y);
            }
        }

        if (DIAG) {
#pragma unroll
            for (int ntl = 0; ntl < 4; ntl++) {
                int kb = st + (c * 4 + ntl) * 8 + 2 * t4;
#pragma unroll
                for (int mt = 0; mt < 2; mt++) {
                    int r0 = qwbase + 16 * mt + g;
                    if (kb     > r0)     s[ntl][mt][0] = -1e30f;
                    if (kb + 1 > r0)     s[ntl][mt][1] = -1e30f;
                    if (kb     > r0 + 8) s[ntl][mt][2] = -1e30f;
                    if (kb + 1 > r0 + 8) s[ntl][mt][3] = -1e30f;
                }
            }
        }

        // ---- online softmax ----
        float cmax[4];
#pragma unroll
        for (int r = 0; r < 4; r++) cmax[r] = -1e30f;
#pragma unroll
        for (int ntl = 0; ntl < 4; ntl++)
#pragma unroll
            for (int mt = 0; mt < 2; mt++) {
                cmax[mt * 2]     = fmaxf(cmax[mt * 2],     fmaxf(s[ntl][mt][0], s[ntl][mt][1]));
                cmax[mt * 2 + 1] = fmaxf(cmax[mt * 2 + 1], fmaxf(s[ntl][mt][2], s[ntl][mt][3]));
            }
#pragma unroll
        for (int r = 0; r < 4; r++) {
            cmax[r] = fmaxf(cmax[r], __shfl_xor_sync(0xffffffffu, cmax[r], 1));
            cmax[r] = fmaxf(cmax[r], __shfl_xor_sync(0xffffffffu, cmax[r], 2));
        }
        float corr[4];
#pragma unroll
        for (int r = 0; r < 4; r++) {
            float mn = fmaxf(m[r], cmax[r]);
            corr[r] = ex2f(m[r] - mn);
            m[r] = mn;
            l[r] *= corr[r];
        }
#pragma unroll
        for (int mt = 0; mt < 2; mt++)
#pragma unroll
            for (int hn = 0; hn < 2; hn++) {
                acc[mt][hn][0] *= corr[mt * 2];
                acc[mt][hn][1] *= corr[mt * 2];
                acc[mt][hn][2] *= corr[mt * 2 + 1];
                acc[mt][hn][3] *= corr[mt * 2 + 1];
            }

        // ---- P = ex2(s-m) -> fp16 A-fragments for PV ----
        uint32_t pa[2][2][4];   // [ks][mt][reg]
#pragma unroll
        for (int ntl = 0; ntl < 4; ntl++) {
            int ks = ntl >> 1;
            int halfn = ntl & 1;
#pragma unroll
            for (int mt = 0; mt < 2; mt++) {
                float p0 = ex2f(s[ntl][mt][0] - m[mt * 2]);
                float p1 = ex2f(s[ntl][mt][1] - m[mt * 2]);
                float p2 = ex2f(s[ntl][mt][2] - m[mt * 2 + 1]);
                float p3 = ex2f(s[ntl][mt][3] - m[mt * 2 + 1]);
                l[mt * 2]     += p0 + p1;
                l[mt * 2 + 1] += p2 + p3;
                pa[ks][mt][0 + 2 * halfn] = cvt_f16x2(p1, p0);
                pa[ks][mt][1 + 2 * halfn] = cvt_f16x2(p3, p2);
            }
        }

        // ---- PV: 2 ksteps x 2 hs-tiles x 2 m-tiles, 1 fp16 mma each ----
#pragma unroll
        for (int ks = 0; ks < 2; ks++) {
            int kstep = c * 2 + ks;
#pragma unroll
            for (int hn = 0; hn < 2; hn++) {
                uint2 vf = sV[kstep][hn][lane];
#pragma unroll
                for (int mt = 0; mt < 2; mt++)
                    mma_f16(acc[mt][hn], pa[ks][mt][0], pa[ks][mt][1], pa[ks][mt][2], pa[ks][mt][3], vf.x, vf.y);
            }
        }
    }

    // ---- reduce l across the 4-thread group ----
#pragma unroll
    for (int r = 0; r < 4; r++) {
        l[r] += __shfl_xor_sync(0xffffffffu, l[r], 1);
        l[r] += __shfl_xor_sync(0xffffffffu, l[r], 2);
    }

    // ---- epilog via smem transpose ----
#pragma unroll
    for (int mt = 0; mt < 2; mt++) {
        int rl = w * 32 + 16 * mt + g;
#pragma unroll
        for (int hn = 0; hn < 2; hn++) {
            int d = hn * 8 + 2 * t4;
            sOut[rl][d]         = acc[mt][hn][0];
            sOut[rl][d + 1]     = acc[mt][hn][1];
            sOut[rl + 8][d]     = acc[mt][hn][2];
            sOut[rl + 8][d + 1] = acc[mt][hn][3];
        }
        sML[rl]     = make_float2(m[mt * 2],     l[mt * 2]);
        sML[rl + 8] = make_float2(m[mt * 2 + 1], l[mt * 2 + 1]);
    }
    __syncthreads();

    size_t pb = ((size_t)(b * NQT + jt) * NKP + kp);
    float4* dst = g_part4 + pb * 4 * 128 + tid;
#pragma unroll
    for (int h = 0; h < 4; h++)
        dst[h * 128] = make_float4(sOut[tid][4 * h], sOut[tid][4 * h + 1],
                                   sOut[tid][4 * h + 2], sOut[tid][4 * h + 3]);
    g_ml[pb * 128 + tid] = sML[tid];
}

__global__ __launch_bounds__(128) void attn_part_kernel()
{
    __shared__ uint2 sK[64][32];       // 64 n-tiles x 8 keys, fp16 frags
    __shared__ uint2 sV[32][2][32];    // 32 ksteps x 2 hs-tiles, fp16 frags
    __shared__ float sOut[128][17];
    __shared__ float2 sML[128];

    int b = blockIdx.y;
    int p = blockIdx.x;
    int jt = 0, rem = p;
    while (rem >= (jt >> 2) + 1) { rem -= (jt >> 2) + 1; jt++; }
    int kp = rem;
    int st = kp * 512;
    int tid = threadIdx.x;

    // ---- prolog: pack K fragments ----
    for (int idx = tid; idx < 64 * 32; idx += 128) {
        int nt = idx >> 5, ln = idx & 31;
        int key = st + nt * 8 + (ln >> 2);
        int d0 = 2 * (ln & 3);
        const float* Kr = g_k + ((size_t)b * TT + key) * HS;
        float2 k0 = *reinterpret_cast<const float2*>(Kr + d0);
        float2 k1 = *reinterpret_cast<const float2*>(Kr + d0 + 8);
        sK[nt][ln] = make_uint2(cvt_f16x2(k0.y, k0.x), cvt_f16x2(k1.y, k1.x));
    }

    // ---- prolog: pack V fragments ----
    for (int idx = tid; idx < 32 * 2 * 32; idx += 128) {
        int ks = idx >> 6, rest = idx & 63;
        int hn = rest >> 5, ln = rest & 31;
        int dim = hn * 8 + (ln >> 2);
        int key0 = st + ks * 16 + 2 * (ln & 3);
        const float* Vb = g_v + (size_t)b * TT * HS + dim;
        float v0 = Vb[(size_t)key0 * HS];
        float v1 = Vb[(size_t)(key0 + 1) * HS];
        float v2 = Vb[(size_t)(key0 + 8) * HS];
        float v3 = Vb[(size_t)(key0 + 9) * HS];
        sV[ks][hn][ln] = make_uint2(cvt_f16x2(v1, v0), cvt_f16x2(v3, v2));
    }
    __syncthreads();

    if (kp == (jt >> 2))
        attn_body<true>(b, jt, kp, sK, sV, sOut, sML);
    else
        attn_body<false>(b, jt, kp, sK, sV, sOut, sML);
}

// ---------------------------------------------------------------------------
// Kernel 3: combine partials (m in log2 domain). n <= 4 supertiles.
// ---------------------------------------------------------------------------
__global__ __launch_bounds__(128) void combine_kernel(float* __restrict__ out)
{
    int jt = blockIdx.x;
    int b  = blockIdx.y;
    int tid = threadIdx.x;
    int n = (jt >> 2) + 1;

    const float4* base = g_part4 + (size_t)(b * NQT + jt) * NKP * 4 * 128 + tid;
    const float2* mlb  = g_ml    + (size_t)(b * NQT + jt) * NKP * 128 + tid;

    float2 ml[NKP];
#pragma unroll
    for (int i = 0; i < NKP; i++)
        ml[i] = (i < n) ? mlb[i * 128] : make_float2(-1e30f, 0.f);

    float m_tot = ml[0].x;
#pragma unroll
    for (int i = 1; i < NKP; i++) m_tot = fmaxf(m_tot, ml[i].x);

    float acc[HS];
#pragma unroll
    for (int h = 0; h < HS; h++) acc[h] = 0.f;
    float l_tot = 0.f;

#pragma unroll 2
    for (int i = 0; i < n; i++) {
        const float4* pp = base + (size_t)i * 4 * 128;
        float4 a0 = pp[0];
        float4 a1 = pp[128];
        float4 a2 = pp[256];
        float4 a3 = pp[384];
        float w = ex2f(ml[i].x - m_tot);
        l_tot = fmaf(ml[i].y, w, l_tot);
        acc[0]  = fmaf(a0.x, w, acc[0]);
        acc[1]  = fmaf(a0.y, w, acc[1]);
        acc[2]  = fmaf(a0.z, w, acc[2]);
        acc[3]  = fmaf(a0.w, w, acc[3]);
        acc[4]  = fmaf(a1.x, w, acc[4]);
        acc[5]  = fmaf(a1.y, w, acc[5]);
        acc[6]  = fmaf(a1.z, w, acc[6]);
        acc[7]  = fmaf(a1.w, w, acc[7]);
        acc[8]  = fmaf(a2.x, w, acc[8]);
        acc[9]  = fmaf(a2.y, w, acc[9]);
        acc[10] = fmaf(a2.z, w, acc[10]);
        acc[11] = fmaf(a2.w, w, acc[11]);
        acc[12] = fmaf(a3.x, w, acc[12]);
        acc[13] = fmaf(a3.y, w, acc[13]);
        acc[14] = fmaf(a3.z, w, acc[14]);
        acc[15] = fmaf(a3.w, w, acc[15]);
    }

    float inv_l = 1.0f / l_tot;
    int t = jt * 128 + tid;
    float4* Or = reinterpret_cast<float4*>(out + ((size_t)b * TT + t) * HS);
#pragma unroll
    for (int j = 0; j < 4; j++)
        Or[j] = make_float4(acc[4 * j] * inv_l, acc[4 * j + 1] * inv_l,
                            acc[4 * j + 2] * inv_l, acc[4 * j + 3] * inv_l);
}

extern "C" void kernel_launch(void* const* d_in, const int* in_sizes, int n_in,
                              void* d_out, int out_size)
{
    const float* x  = (const float*)d_in[0];
    const float* wq = (const float*)d_in[1];
    const float* wk = (const float*)d_in[2];
    const float* wv = (const float*)d_in[3];
    float* out = (float*)d_out;

    rope_table_kernel<<<(TT * 8) / 128, 128>>>();

    dim3 grid_q(256, 2);
    qkv_rope_kernel<<<grid_q, 128>>>(x, wq, wk, wv);

    dim3 grid_p(NPAIR4, BB);
    attn_part_kernel<<<grid_p, 128>>>();

    dim3 grid_c(NQT, BB);
    combine_kernel<<<grid_c, 128>>>(out);
}

// round 11
// speedup vs baseline: 2.1816x; 1.1007x over previous
#include <cuda_runtime.h>
#include <math.h>
#include <stdint.h>

#define BB 16
#define TT 2048
#define EE 64
#define HS 16
#define NQT (TT / 128)    // 16 query tiles
#define NKP 4             // max 512-key supertiles per query tile
#define NPAIR4 40         // sum_{jt=0..15} (jt/4 + 1)

// log2(e) * hs^-0.5
#define QSCALE 0.360673760222241f
// fixed softmax shift (log2 domain); scores are ~±1, safe up to ~100
#define MFIX 4.0f

// scratch
__device__ float g_q[BB * TT * HS];
__device__ float g_k[BB * TT * HS];
__device__ float g_v[BB * TT * HS];
__device__ float g_rope[TT * HS];
// partials: acc as 4 coalesced float4 fields, plus l (scalar, fixed-max domain)
__device__ float4 g_part4[BB * NQT * NKP * 4 * 128];
__device__ float g_l[BB * NQT * NKP * 128];

// ---- helpers ----
__device__ __forceinline__ float ex2f(float x) {
    float y; asm("ex2.approx.f32 %0,%1;" : "=f"(y) : "f"(x)); return y;
}
// first operand -> HIGH half, second -> LOW half
__device__ __forceinline__ uint32_t cvt_f16x2(float hi, float lo) {
    uint32_t d; asm("cvt.rn.f16x2.f32 %0,%1,%2;" : "=r"(d) : "f"(hi), "f"(lo)); return d;
}
__device__ __forceinline__ void mma_f16(float c[4],
    uint32_t a0, uint32_t a1, uint32_t a2, uint32_t a3, uint32_t b0, uint32_t b1) {
    asm volatile(
        "mma.sync.aligned.m16n8k16.row.col.f32.f16.f16.f32 "
        "{%0,%1,%2,%3},{%4,%5,%6,%7},{%8,%9},{%0,%1,%2,%3};"
        : "+f"(c[0]), "+f"(c[1]), "+f"(c[2]), "+f"(c[3])
        : "r"(a0), "r"(a1), "r"(a2), "r"(a3), "r"(b0), "r"(b1));
}

// ---------------------------------------------------------------------------
// Kernel 0: RoPE cos/sin table
// ---------------------------------------------------------------------------
__global__ __launch_bounds__(128) void rope_table_kernel()
{
    int idx = blockIdx.x * 128 + threadIdx.x;
    int t = idx >> 3;
    int i = idx & 7;
    float inv = powf(10000.0f, -(float)i * (2.0f / (float)HS));
    float sn, cs;
    sincosf((float)t * inv, &sn, &cs);
    g_rope[t * 16 + 2 * i]     = cs;
    g_rope[t * 16 + 2 * i + 1] = sn;
}

// ---------------------------------------------------------------------------
// Kernel 1: fused QKV projection + RoPE. One thread per (row, half).
// ---------------------------------------------------------------------------
__global__ __launch_bounds__(128) void qkv_rope_kernel(
    const float* __restrict__ x,
    const float* __restrict__ wq,
    const float* __restrict__ wk,
    const float* __restrict__ wv)
{
    __shared__ float swq[EE * 8];
    __shared__ float swk[EE * 8];
    __shared__ float swv[EE * 8];

    int tid = threadIdx.x;
    int half = blockIdx.y;
    int hbase = half * 8;

    for (int i = tid; i < EE * 8; i += 128) {
        int e = i >> 3, h = i & 7;
        swq[i] = wq[e * HS + hbase + h];
        swk[i] = wk[e * HS + hbase + h];
        swv[i] = wv[e * HS + hbase + h];
    }
    __syncthreads();

    int row = blockIdx.x * 128 + tid;
    int t = row & (TT - 1);

    const float4* xr = reinterpret_cast<const float4*>(x + (size_t)row * EE);

    float q[8], k[8], v[8];
#pragma unroll
    for (int h = 0; h < 8; h++) { q[h] = 0.f; k[h] = 0.f; v[h] = 0.f; }

#pragma unroll
    for (int e4 = 0; e4 < EE / 4; e4++) {
        float4 xv = xr[e4];
        float xs[4] = {xv.x, xv.y, xv.z, xv.w};
#pragma unroll
        for (int j = 0; j < 4; j++) {
            int e = e4 * 4 + j;
#pragma unroll
            for (int h = 0; h < 8; h++) {
                q[h] = fmaf(xs[j], swq[e * 8 + h], q[h]);
                k[h] = fmaf(xs[j], swk[e * 8 + h], k[h]);
                v[h] = fmaf(xs[j], swv[e * 8 + h], v[h]);
            }
        }
    }

    const float4* rp = reinterpret_cast<const float4*>(g_rope + t * 16 + hbase);
    float rope[8];
    {
        float4 r0 = rp[0], r1 = rp[1];
        rope[0] = r0.x; rope[1] = r0.y; rope[2] = r0.z; rope[3] = r0.w;
        rope[4] = r1.x; rope[5] = r1.y; rope[6] = r1.z; rope[7] = r1.w;
    }

    float qo[8], ko[8];
#pragma unroll
    for (int i = 0; i < 4; i++) {
        float cs = rope[2 * i], sn = rope[2 * i + 1];
        float qe = q[2 * i], qd = q[2 * i + 1];
        float ke = k[2 * i], kd = k[2 * i + 1];
        qo[2 * i]     = qe * cs - qd * sn;
        qo[2 * i + 1] = qe * sn + qd * cs;
        ko[2 * i]     = ke * cs - kd * sn;
        ko[2 * i + 1] = ke * sn + kd * cs;
    }

    float4* Q4 = reinterpret_cast<float4*>(g_q + (size_t)row * HS + hbase);
    float4* K4 = reinterpret_cast<float4*>(g_k + (size_t)row * HS + hbase);
    float4* V4 = reinterpret_cast<float4*>(g_v + (size_t)row * HS + hbase);
    Q4[0] = make_float4(qo[0], qo[1], qo[2], qo[3]);
    Q4[1] = make_float4(qo[4], qo[5], qo[6], qo[7]);
    K4[0] = make_float4(ko[0], ko[1], ko[2], ko[3]);
    K4[1] = make_float4(ko[4], ko[5], ko[6], ko[7]);
    V4[0] = make_float4(v[0], v[1], v[2], v[3]);
    V4[1] = make_float4(v[4], v[5], v[6], v[7]);
}

// ---------------------------------------------------------------------------
// Kernel 2: tensor-core flash attention partial, fixed-max softmax.
// One block per (b, jt, 512-key supertile). 4 warps x 32 queries.
// ---------------------------------------------------------------------------
template <bool DIAG>
__device__ __forceinline__ void attn_body(
    int b, int jt, int kp,
    const uint2 (*sK)[32], const uint2 (*sV)[2][32],
    float (*sOut)[17], float* sL)
{
    int tid = threadIdx.x;
    int w = tid >> 5;
    int lane = tid & 31;
    int g = lane >> 2;
    int t4 = lane & 3;
    int st = kp * 512;
    int qwbase = jt * 128 + w * 32;

    // ---- load Q fragments (fp16, scaled by QSCALE) ----
    uint32_t qA[2][4];
#pragma unroll
    for (int mt = 0; mt < 2; mt++) {
        int r0 = qwbase + 16 * mt + g;
        const float* Q0 = g_q + ((size_t)b * TT + r0) * HS;
        const float* Q1 = g_q + ((size_t)b * TT + r0 + 8) * HS;
        float2 f00 = *reinterpret_cast<const float2*>(Q0 + 2 * t4);
        float2 f01 = *reinterpret_cast<const float2*>(Q0 + 2 * t4 + 8);
        float2 f10 = *reinterpret_cast<const float2*>(Q1 + 2 * t4);
        float2 f11 = *reinterpret_cast<const float2*>(Q1 + 2 * t4 + 8);
        qA[mt][0] = cvt_f16x2(f00.y * QSCALE, f00.x * QSCALE);
        qA[mt][1] = cvt_f16x2(f10.y * QSCALE, f10.x * QSCALE);
        qA[mt][2] = cvt_f16x2(f01.y * QSCALE, f01.x * QSCALE);
        qA[mt][3] = cvt_f16x2(f11.y * QSCALE, f11.x * QSCALE);
    }

    float l[4], acc[2][2][4];
#pragma unroll
    for (int r = 0; r < 4; r++) l[r] = 0.f;
#pragma unroll
    for (int mt = 0; mt < 2; mt++)
#pragma unroll
        for (int hn = 0; hn < 2; hn++)
#pragma unroll
            for (int r = 0; r < 4; r++) acc[mt][hn][r] = 0.f;

    int nchunks = 16;
    if (DIAG) {
        int qmaxw = qwbase + 31;
        nchunks = ((qmaxw - st) >> 5) + 1;
        if (nchunks > 16) nchunks = 16;
    }

    for (int c = 0; c < nchunks; c++) {
        // ---- QK^T: 4 n-tiles x 2 m-tiles, 1 fp16 mma each ----
        float s[4][2][4];
#pragma unroll
        for (int ntl = 0; ntl < 4; ntl++) {
            int nt = c * 4 + ntl;
            uint2 kf = sK[nt][lane];
#pragma unroll
            for (int mt = 0; mt < 2; mt++) {
                s[ntl][mt][0] = 0.f; s[ntl][mt][1] = 0.f;
                s[ntl][mt][2] = 0.f; s[ntl][mt][3] = 0.f;
                mma_f16(s[ntl][mt], qA[mt][0], qA[mt][1], qA[mt][2], qA[mt][3], kf.x, kf.y);
            }
        }

        if (DIAG) {
#pragma unroll
            for (int ntl = 0; ntl < 4; ntl++) {
                int kb = st + (c * 4 + ntl) * 8 + 2 * t4;
#pragma unroll
                for (int mt = 0; mt < 2; mt++) {
                    int r0 = qwbase + 16 * mt + g;
                    if (kb     > r0)     s[ntl][mt][0] = -1e30f;
                    if (kb + 1 > r0)     s[ntl][mt][1] = -1e30f;
                    if (kb     > r0 + 8) s[ntl][mt][2] = -1e30f;
                    if (kb + 1 > r0 + 8) s[ntl][mt][3] = -1e30f;
                }
            }
        }

        // ---- P = ex2(s - MFIX), no running max needed (scores bounded) ----
        uint32_t pa[2][2][4];   // [ks][mt][reg]
#pragma unroll
        for (int ntl = 0; ntl < 4; ntl++) {
            int ks = ntl >> 1;
            int halfn = ntl & 1;
#pragma unroll
            for (int mt = 0; mt < 2; mt++) {
                float p0 = ex2f(s[ntl][mt][0] - MFIX);
                float p1 = ex2f(s[ntl][mt][1] - MFIX);
                float p2 = ex2f(s[ntl][mt][2] - MFIX);
                float p3 = ex2f(s[ntl][mt][3] - MFIX);
                l[mt * 2]     += p0 + p1;
                l[mt * 2 + 1] += p2 + p3;
                pa[ks][mt][0 + 2 * halfn] = cvt_f16x2(p1, p0);
                pa[ks][mt][1 + 2 * halfn] = cvt_f16x2(p3, p2);
            }
        }

        // ---- PV: 2 ksteps x 2 hs-tiles x 2 m-tiles, 1 fp16 mma each ----
#pragma unroll
        for (int ks = 0; ks < 2; ks++) {
            int kstep = c * 2 + ks;
#pragma unroll
            for (int hn = 0; hn < 2; hn++) {
                uint2 vf = sV[kstep][hn][lane];
#pragma unroll
                for (int mt = 0; mt < 2; mt++)
                    mma_f16(acc[mt][hn], pa[ks][mt][0], pa[ks][mt][1], pa[ks][mt][2], pa[ks][mt][3], vf.x, vf.y);
            }
        }
    }

    // ---- reduce l across the 4-thread group (once per supertile) ----
#pragma unroll
    for (int r = 0; r < 4; r++) {
        l[r] += __shfl_xor_sync(0xffffffffu, l[r], 1);
        l[r] += __shfl_xor_sync(0xffffffffu, l[r], 2);
    }

    // ---- epilog via smem transpose ----
#pragma unroll
    for (int mt = 0; mt < 2; mt++) {
        int rl = w * 32 + 16 * mt + g;
#pragma unroll
        for (int hn = 0; hn < 2; hn++) {
            int d = hn * 8 + 2 * t4;
            sOut[rl][d]         = acc[mt][hn][0];
            sOut[rl][d + 1]     = acc[mt][hn][1];
            sOut[rl + 8][d]     = acc[mt][hn][2];
            sOut[rl + 8][d + 1] = acc[mt][hn][3];
        }
        if (t4 == 0) {
            sL[rl]     = l[mt * 2];
            sL[rl + 8] = l[mt * 2 + 1];
        }
    }
    __syncthreads();

    size_t pb = ((size_t)(b * NQT + jt) * NKP + kp);
    float4* dst = g_part4 + pb * 4 * 128 + tid;
#pragma unroll
    for (int h = 0; h < 4; h++)
        dst[h * 128] = make_float4(sOut[tid][4 * h], sOut[tid][4 * h + 1],
                                   sOut[tid][4 * h + 2], sOut[tid][4 * h + 3]);
    g_l[pb * 128 + tid] = sL[tid];
}

__global__ __launch_bounds__(128) void attn_part_kernel()
{
    __shared__ uint2 sK[64][32];       // 64 n-tiles x 8 keys, fp16 frags
    __shared__ uint2 sV[32][2][32];    // 32 ksteps x 2 hs-tiles, fp16 frags
    __shared__ float sOut[128][17];
    __shared__ float sL[128];

    int b = blockIdx.y;
    int p = blockIdx.x;
    int jt = 0, rem = p;
    while (rem >= (jt >> 2) + 1) { rem -= (jt >> 2) + 1; jt++; }
    int kp = rem;
    int st = kp * 512;
    int tid = threadIdx.x;

    // ---- prolog: pack K fragments ----
    for (int idx = tid; idx < 64 * 32; idx += 128) {
        int nt = idx >> 5, ln = idx & 31;
        int key = st + nt * 8 + (ln >> 2);
        int d0 = 2 * (ln & 3);
        const float* Kr = g_k + ((size_t)b * TT + key) * HS;
        float2 k0 = *reinterpret_cast<const float2*>(Kr + d0);
        float2 k1 = *reinterpret_cast<const float2*>(Kr + d0 + 8);
        sK[nt][ln] = make_uint2(cvt_f16x2(k0.y, k0.x), cvt_f16x2(k1.y, k1.x));
    }

    // ---- prolog: pack V fragments ----
    for (int idx = tid; idx < 32 * 2 * 32; idx += 128) {
        int ks = idx >> 6, rest = idx & 63;
        int hn = rest >> 5, ln = rest & 31;
        int dim = hn * 8 + (ln >> 2);
        int key0 = st + ks * 16 + 2 * (ln & 3);
        const float* Vb = g_v + (size_t)b * TT * HS + dim;
        float v0 = Vb[(size_t)key0 * HS];
        float v1 = Vb[(size_t)(key0 + 1) * HS];
        float v2 = Vb[(size_t)(key0 + 8) * HS];
        float v3 = Vb[(size_t)(key0 + 9) * HS];
        sV[ks][hn][ln] = make_uint2(cvt_f16x2(v1, v0), cvt_f16x2(v3, v2));
    }
    __syncthreads();

    if (kp == (jt >> 2))
        attn_body<true>(b, jt, kp, sK, sV, sOut, sL);
    else
        attn_body<false>(b, jt, kp, sK, sV, sOut, sL);
}

// ---------------------------------------------------------------------------
// Kernel 3: combine partials: plain sums (fixed-max domain). n <= 4.
// ---------------------------------------------------------------------------
__global__ __launch_bounds__(128) void combine_kernel(float* __restrict__ out)
{
    int jt = blockIdx.x;
    int b  = blockIdx.y;
    int tid = threadIdx.x;
    int n = (jt >> 2) + 1;

    const float4* base = g_part4 + (size_t)(b * NQT + jt) * NKP * 4 * 128 + tid;
    const float*  lb   = g_l     + (size_t)(b * NQT + jt) * NKP * 128 + tid;

    float acc[HS];
#pragma unroll
    for (int h = 0; h < HS; h++) acc[h] = 0.f;
    float l_tot = 0.f;

#pragma unroll 2
    for (int i = 0; i < n; i++) {
        const float4* pp = base + (size_t)i * 4 * 128;
        float4 a0 = pp[0];
        float4 a1 = pp[128];
        float4 a2 = pp[256];
        float4 a3 = pp[384];
        l_tot += lb[i * 128];
        acc[0]  += a0.x; acc[1]  += a0.y; acc[2]  += a0.z; acc[3]  += a0.w;
        acc[4]  += a1.x; acc[5]  += a1.y; acc[6]  += a1.z; acc[7]  += a1.w;
        acc[8]  += a2.x; acc[9]  += a2.y; acc[10] += a2.z; acc[11] += a2.w;
        acc[12] += a3.x; acc[13] += a3.y; acc[14] += a3.z; acc[15] += a3.w;
    }

    float inv_l = 1.0f / l_tot;
    int t = jt * 128 + tid;
    float4* Or = reinterpret_cast<float4*>(out + ((size_t)b * TT + t) * HS);
#pragma unroll
    for (int j = 0; j < 4; j++)
        Or[j] = make_float4(acc[4 * j] * inv_l, acc[4 * j + 1] * inv_l,
                            acc[4 * j + 2] * inv_l, acc[4 * j + 3] * inv_l);
}

extern "C" void kernel_launch(void* const* d_in, const int* in_sizes, int n_in,
                              void* d_out, int out_size)
{
    const float* x  = (const float*)d_in[0];
    const float* wq = (const float*)d_in[1];
    const float* wk = (const float*)d_in[2];
    const float* wv = (const float*)d_in[3];
    float* out = (float*)d_out;

    rope_table_kernel<<<(TT * 8) / 128, 128>>>();

    dim3 grid_q(256, 2);
    qkv_rope_kernel<<<grid_q, 128>>>(x, wq, wk, wv);

    dim3 grid_p(NPAIR4, BB);
    attn_part_kernel<<<grid_p, 128>>>();

    dim3 grid_c(NQT, BB);
    combine_kernel<<<grid_c, 128>>>(out);
}